// round 3
// baseline (speedup 1.0000x reference)
#include <cuda_runtime.h>
#include <math_constants.h>
#include <cstdint>

// FLoss: weighted BCE, weights = W / (dist_to_argmax_centroid + 1)
// input  d_in[0]: [B,1,T,W,W] f32  (same linear layout as [B,T,W,W])
// target d_in[1]: [B,T,W,W]   f32
// out: scalar f32 = -mean(w * (t*clip(log p,-100) + (1-t)*clip(log1p(-p),-100)))

#define WDIM 256
#define FRAME_ELEMS (WDIM * WDIM)          // 65536
#define FRAME_ELEMS4 (FRAME_ELEMS / 4)     // 16384
#define MAX_FRAMES 4096

__device__ float    g_cx[MAX_FRAMES];
__device__ float    g_cy[MAX_FRAMES];
__device__ double   g_acc;
__device__ unsigned g_done;

// ---------------------------------------------------------------------------
// Kernel 1: per-frame max + centroid of maximal pixels, single pass.
// One CTA (1024 threads) per frame; 16x float4 per thread.
// Four INDEPENDENT running-max chains (one per float4 lane) with branchless
// select updates: no BSSY/BSYNC, 1/4 the serial dependence length.
// Exact float-equality tie handling, identical to reference (target == max).
// ---------------------------------------------------------------------------
__global__ __launch_bounds__(1024) void frame_stats_kernel(const float* __restrict__ tgt)
{
    const int f   = blockIdx.x;
    const int tid = threadIdx.x;
    const float4* base = reinterpret_cast<const float4*>(tgt) + (size_t)f * FRAME_ELEMS4;

    float lm[4], cn[4], sx[4], sy[4];
    #pragma unroll
    for (int c = 0; c < 4; c++) { lm[c] = -CUDART_INF_F; cn[c] = 0.f; sx[c] = 0.f; sy[c] = 0.f; }

    #pragma unroll
    for (int k = 0; k < 16; k++) {
        const int e4 = tid + k * 1024;
        const float4 v = __ldg(base + e4);
        const int e = e4 * 4;
        const float row  = (float)(e >> 8);
        const float col0 = (float)(e & 255);
        const float vals[4] = {v.x, v.y, v.z, v.w};
        #pragma unroll
        for (int c = 0; c < 4; c++) {
            const float val = vals[c];
            const float col = col0 + (float)c;
            const bool gt = (val >  lm[c]);
            const bool eq = (val == lm[c]);
            // branchless: new-max resets, tie accumulates, else keep
            cn[c] = gt ? 1.f : (cn[c] + (eq ? 1.f : 0.f));
            sx[c] = gt ? row : (sx[c] + (eq ? row : 0.f));
            sy[c] = gt ? col : (sy[c] + (eq ? col : 0.f));
            lm[c] = fmaxf(lm[c], val);
        }
    }

    // merge the 4 chains into one (cheap, once per thread)
    float lmax = lm[0], cnt = cn[0], tsx = sx[0], tsy = sy[0];
    #pragma unroll
    for (int c = 1; c < 4; c++) {
        if (lm[c] > lmax)       { lmax = lm[c]; cnt = cn[c]; tsx = sx[c]; tsy = sy[c]; }
        else if (lm[c] == lmax) { cnt += cn[c]; tsx += sx[c]; tsy += sy[c]; }
    }

    // block max reduction
    __shared__ float s_wmax[32];
    __shared__ float s_gmax;
    __shared__ float s_sx, s_sy, s_cnt;

    float wm = lmax;
    #pragma unroll
    for (int o = 16; o; o >>= 1) wm = fmaxf(wm, __shfl_xor_sync(0xffffffffu, wm, o));
    if ((tid & 31) == 0) s_wmax[tid >> 5] = wm;
    if (tid == 0) { s_sx = 0.f; s_sy = 0.f; s_cnt = 0.f; }
    __syncthreads();
    if (tid < 32) {
        float m = s_wmax[tid];
        #pragma unroll
        for (int o = 16; o; o >>= 1) m = fmaxf(m, __shfl_xor_sync(0xffffffffu, m, o));
        if (tid == 0) s_gmax = m;
    }
    __syncthreads();

    if (lmax == s_gmax) {
        atomicAdd(&s_cnt, cnt);
        atomicAdd(&s_sx,  tsx);
        atomicAdd(&s_sy,  tsy);
    }
    __syncthreads();

    if (tid == 0) {
        g_cx[f] = s_sx / s_cnt;
        g_cy[f] = s_sy / s_cnt;
        if (f == 0) { g_acc = 0.0; g_done = 0u; }   // per-replay reset (runs before loss)
    }
}

// ---------------------------------------------------------------------------
// Kernel 2: weighted BCE accumulation + last-block finalize.
// Grid-stride over 8-element chunks (2x float4 from each array -> MLP=4).
// ---------------------------------------------------------------------------
__global__ __launch_bounds__(256) void loss_kernel(const float* __restrict__ inp,
                                                   const float* __restrict__ tgt,
                                                   int total8,
                                                   float* __restrict__ out,
                                                   double inv_n)
{
    __shared__ double s_acc;
    if (threadIdx.x == 0) s_acc = 0.0;
    __syncthreads();

    const float4* P = reinterpret_cast<const float4*>(inp);
    const float4* T = reinterpret_cast<const float4*>(tgt);

    float lsum = 0.f;
    const int stride = gridDim.x * blockDim.x;
    for (int i = blockIdx.x * blockDim.x + threadIdx.x; i < total8; i += stride) {
        const int f = i >> 13;                 // 8192 8-chunks per frame
        const float cx = __ldg(&g_cx[f]);
        const float cy = __ldg(&g_cy[f]);

        const int e = i << 3;                  // 8 consecutive elems, same row
        const float row  = (float)((e >> 8) & 255);
        const float col0 = (float)(e & 255);

        const float4 p0 = __ldg(P + 2 * i);
        const float4 p1 = __ldg(P + 2 * i + 1);
        const float4 t0 = __ldg(T + 2 * i);
        const float4 t1 = __ldg(T + 2 * i + 1);

        const float di  = row - cx;
        const float di2 = di * di;

        const float pv[8] = {p0.x, p0.y, p0.z, p0.w, p1.x, p1.y, p1.z, p1.w};
        const float tv[8] = {t0.x, t0.y, t0.z, t0.w, t1.x, t1.y, t1.z, t1.w};

        #pragma unroll
        for (int c = 0; c < 8; c++) {
            const float dj = (col0 + (float)c) - cy;
            const float s  = fmaf(dj, dj, di2);
            float dist;
            asm("sqrt.approx.f32 %0, %1;" : "=f"(dist) : "f"(s));   // sqrt.approx(0)=0
            const float wgt = __fdividef(256.0f, dist + 1.0f);

            const float p = pv[c];
            const float t = tv[c];
            const float lp = fmaxf(__logf(p),        -100.0f);
            const float lq = fmaxf(__logf(1.0f - p), -100.0f);
            const float term = fmaf(t, lp - lq, lq);   // t*lp + (1-t)*lq
            lsum = fmaf(wgt, term, lsum);
        }
    }

    // warp reduce -> smem double -> global double
    #pragma unroll
    for (int o = 16; o; o >>= 1) lsum += __shfl_xor_sync(0xffffffffu, lsum, o);
    if ((threadIdx.x & 31) == 0) atomicAdd(&s_acc, (double)lsum);
    __syncthreads();

    if (threadIdx.x == 0) {
        atomicAdd(&g_acc, s_acc);
        __threadfence();
        const unsigned t = atomicAdd(&g_done, 1u);
        if (t == gridDim.x - 1) {                      // last block finalizes
            const double total = atomicAdd(&g_acc, 0.0);
            out[0] = (float)(-total * inv_n);
        }
    }
}

extern "C" void kernel_launch(void* const* d_in, const int* in_sizes, int n_in,
                              void* d_out, int out_size)
{
    const float* inp = (const float*)d_in[0];
    const float* tgt = (const float*)d_in[1];
    float* out = (float*)d_out;

    const int n       = in_sizes[1];       // B*T*W*W
    const int nframes = n >> 16;
    const int total8  = n >> 3;

    frame_stats_kernel<<<nframes, 1024>>>(tgt);

    const int grid = 148 * 8;              // 1184 CTAs x 256 thr, ~7 iters/thread
    loss_kernel<<<grid, 256>>>(inp, tgt, total8, out, 1.0 / (double)n);
}

// round 4
// speedup vs baseline: 1.1174x; 1.1174x over previous
#include <cuda_runtime.h>
#include <math_constants.h>
#include <cstdint>

// FLoss: weighted BCE, weights = W / (dist_to_argmax_centroid + 1)
// input  d_in[0]: [B,1,T,W,W] f32  (same linear layout as [B,T,W,W])
// target d_in[1]: [B,T,W,W]   f32
// out: scalar f32 = -mean(w * (t*clip(log p,-100) + (1-t)*clip(log1p(-p),-100)))

#define WDIM 256
#define FRAME_ELEMS (WDIM * WDIM)          // 65536
#define FRAME_ELEMS4 (FRAME_ELEMS / 4)     // 16384
#define TILES_PER_FRAME 8                  // 2048 float4 per tile
#define TILE_F4 (FRAME_ELEMS4 / TILES_PER_FRAME)
#define MAX_FRAMES 4096

__device__ float    g_cx[MAX_FRAMES];
__device__ float    g_cy[MAX_FRAMES];
__device__ double   g_acc;
__device__ unsigned g_done;

// ---------------------------------------------------------------------------
// Kernel 1: per-frame max + centroid of maximal pixels, single pass.
// One CTA (1024 threads) per frame; 16x float4 per thread, 4 independent
// branchless running-max chains. Exact tie semantics (target == max).
// Reads with default policy -> target stays resident in L2 for the loss pass.
// ---------------------------------------------------------------------------
__global__ __launch_bounds__(1024) void frame_stats_kernel(const float* __restrict__ tgt)
{
    const int f   = blockIdx.x;
    const int tid = threadIdx.x;
    const float4* base = reinterpret_cast<const float4*>(tgt) + (size_t)f * FRAME_ELEMS4;

    float lm[4], cn[4], sx[4], sy[4];
    #pragma unroll
    for (int c = 0; c < 4; c++) { lm[c] = -CUDART_INF_F; cn[c] = 0.f; sx[c] = 0.f; sy[c] = 0.f; }

    #pragma unroll
    for (int k = 0; k < 16; k++) {
        const int e4 = tid + k * 1024;
        const float4 v = __ldg(base + e4);
        const int e = e4 * 4;
        const float row  = (float)(e >> 8);
        const float col0 = (float)(e & 255);
        const float vals[4] = {v.x, v.y, v.z, v.w};
        #pragma unroll
        for (int c = 0; c < 4; c++) {
            const float val = vals[c];
            const float col = col0 + (float)c;
            const bool gt = (val >  lm[c]);
            const bool eq = (val == lm[c]);
            cn[c] = gt ? 1.f : (cn[c] + (eq ? 1.f : 0.f));
            sx[c] = gt ? row : (sx[c] + (eq ? row : 0.f));
            sy[c] = gt ? col : (sy[c] + (eq ? col : 0.f));
            lm[c] = fmaxf(lm[c], val);
        }
    }

    float lmax = lm[0], cnt = cn[0], tsx = sx[0], tsy = sy[0];
    #pragma unroll
    for (int c = 1; c < 4; c++) {
        if (lm[c] > lmax)       { lmax = lm[c]; cnt = cn[c]; tsx = sx[c]; tsy = sy[c]; }
        else if (lm[c] == lmax) { cnt += cn[c]; tsx += sx[c]; tsy += sy[c]; }
    }

    __shared__ float s_wmax[32];
    __shared__ float s_gmax;
    __shared__ float s_sx, s_sy, s_cnt;

    float wm = lmax;
    #pragma unroll
    for (int o = 16; o; o >>= 1) wm = fmaxf(wm, __shfl_xor_sync(0xffffffffu, wm, o));
    if ((tid & 31) == 0) s_wmax[tid >> 5] = wm;
    if (tid == 0) { s_sx = 0.f; s_sy = 0.f; s_cnt = 0.f; }
    __syncthreads();
    if (tid < 32) {
        float m = s_wmax[tid];
        #pragma unroll
        for (int o = 16; o; o >>= 1) m = fmaxf(m, __shfl_xor_sync(0xffffffffu, m, o));
        if (tid == 0) s_gmax = m;
    }
    __syncthreads();

    if (lmax == s_gmax) {
        atomicAdd(&s_cnt, cnt);
        atomicAdd(&s_sx,  tsx);
        atomicAdd(&s_sy,  tsy);
    }
    __syncthreads();

    if (tid == 0) {
        g_cx[f] = s_sx / s_cnt;
        g_cy[f] = s_sy / s_cnt;
        if (f == 0) { g_acc = 0.0; g_done = 0u; }   // per-replay reset (runs before loss)
    }
}

// ---------------------------------------------------------------------------
// Kernel 2: weighted BCE, per-frame tiled (8 CTAs/frame), log2-domain math.
// input read with __ldcs (evict-first) so it does not evict the L2-resident
// target; target read with __ldg (should hit L2 from frame_stats pass).
// Last CTA finalizes the scalar output.
// ---------------------------------------------------------------------------
#define LOG2_CLAMP (-144.26950408889634f)   // -100 / ln(2)
#define LN2F        (0.6931471805599453f)

__global__ __launch_bounds__(256, 4) void loss_kernel(const float* __restrict__ inp,
                                                      const float* __restrict__ tgt,
                                                      float* __restrict__ out,
                                                      double inv_n)
{
    const int tile = blockIdx.x;
    const int f    = tile >> 3;            // TILES_PER_FRAME == 8
    const int t_in = tile & 7;
    const float cx = g_cx[f];
    const float cy = g_cy[f];

    const float4* P = reinterpret_cast<const float4*>(inp) + (size_t)f * FRAME_ELEMS4 + t_in * TILE_F4;
    const float4* T = reinterpret_cast<const float4*>(tgt) + (size_t)f * FRAME_ELEMS4 + t_in * TILE_F4;
    const int ebase = t_in * (TILE_F4 * 4);  // element offset of tile within frame

    float lsum = 0.f;

    #pragma unroll
    for (int k = 0; k < 8; k++) {
        const int idx4 = k * 256 + threadIdx.x;
        const float4 p4 = __ldcs(P + idx4);      // streaming: evict-first in L2
        const float4 t4 = __ldg (T + idx4);      // expect L2 hit

        const int e = ebase + idx4 * 4;
        const float row  = (float)(e >> 8);
        const float col0 = (float)(e & 255);
        const float di   = row - cx;
        const float di2  = di * di;

        const float pv[4] = {p4.x, p4.y, p4.z, p4.w};
        const float tv[4] = {t4.x, t4.y, t4.z, t4.w};

        #pragma unroll
        for (int c = 0; c < 4; c++) {
            const float dj = (col0 + (float)c) - cy;
            const float s  = fmaf(dj, dj, di2);
            float dist;
            asm("sqrt.approx.f32 %0, %1;" : "=f"(dist) : "f"(s));
            const float wgt = __fdividef(256.0f, dist + 1.0f);

            const float p = pv[c];
            const float t = tv[c];
            float lp2, lq2;
            asm("lg2.approx.f32 %0, %1;" : "=f"(lp2) : "f"(p));
            asm("lg2.approx.f32 %0, %1;" : "=f"(lq2) : "f"(1.0f - p));
            lp2 = fmaxf(lp2, LOG2_CLAMP);
            lq2 = fmaxf(lq2, LOG2_CLAMP);
            const float term = fmaf(t, lp2 - lq2, lq2);   // log2 domain
            lsum = fmaf(wgt, term, lsum);
        }
    }

    lsum *= LN2F;   // back to natural-log domain, once per thread

    __shared__ double s_acc;
    if (threadIdx.x == 0) s_acc = 0.0;
    __syncthreads();

    #pragma unroll
    for (int o = 16; o; o >>= 1) lsum += __shfl_xor_sync(0xffffffffu, lsum, o);
    if ((threadIdx.x & 31) == 0) atomicAdd(&s_acc, (double)lsum);
    __syncthreads();

    if (threadIdx.x == 0) {
        atomicAdd(&g_acc, s_acc);
        __threadfence();
        const unsigned t = atomicAdd(&g_done, 1u);
        if (t == gridDim.x - 1) {
            const double total = atomicAdd(&g_acc, 0.0);
            out[0] = (float)(-total * inv_n);
        }
    }
}

extern "C" void kernel_launch(void* const* d_in, const int* in_sizes, int n_in,
                              void* d_out, int out_size)
{
    const float* inp = (const float*)d_in[0];
    const float* tgt = (const float*)d_in[1];
    float* out = (float*)d_out;

    const int n       = in_sizes[1];       // B*T*W*W
    const int nframes = n >> 16;

    frame_stats_kernel<<<nframes, 1024>>>(tgt);
    loss_kernel<<<nframes * TILES_PER_FRAME, 256>>>(inp, tgt, out, 1.0 / (double)n);
}